// round 9
// baseline (speedup 1.0000x reference)
#include <cuda_runtime.h>
#include <cuda_bf16.h>
#include <cstdint>

// ---------------- problem constants ----------------
#define BATCH 2
#define S     2048
#define DM    1024
#define H     16
#define HD    64
#define TDM   3072          // 3*DM
#define FFN   4096
#define TOK   4096          // BATCH*S
#define EPS   1e-5f

// ---------------- scratch (static __device__, allocation-free) ----------------
__device__ float g_tmp[(size_t)TOK * DM];
__device__ float g_h[(size_t)TOK * DM];

// bf16 hi/lo planes
__device__ __align__(16) __nv_bfloat16 g_wbf[25165824];    // all weights, 50 MB
#define WQKV_HI 0ull
#define WQKV_LO 3145728ull
#define WO_HI   6291456ull
#define WO_LO   7340032ull
#define W1_HI   8388608ull
#define W1_LO   12582912ull
#define W2_HI   16777216ull
#define W2_LO   20971520ull
__device__ __align__(16) __nv_bfloat16 g_xbf[8388608];     // x hi/lo planes
__device__ __align__(16) __nv_bfloat16 g_qkvbf[25165824];  // qkv hi/lo planes
__device__ __align__(16) __nv_bfloat16 g_ctxbf[8388608];
__device__ __align__(16) __nv_bfloat16 g_hbf[8388608];
__device__ __align__(16) __nv_bfloat16 g_ffnbf[33554432];  // ffn hi/lo planes

// ======================= helpers =======================
__device__ __forceinline__ uint32_t smem_u32(const void* p) {
    uint32_t a;
    asm("{ .reg .u64 t; cvta.to.shared.u64 t, %1; cvt.u32.u64 %0, t; }" : "=r"(a) : "l"(p));
    return a;
}
#define CP_COMMIT() asm volatile("cp.async.commit_group;" ::: "memory")
#define CP_WAIT2()  asm volatile("cp.async.wait_group 2;" ::: "memory")
#define CP_WAIT1()  asm volatile("cp.async.wait_group 1;" ::: "memory")

__device__ __forceinline__ void cp_async16(uint32_t dst, const void* src) {
    asm volatile("cp.async.ca.shared.global [%0], [%1], 16;"
                 :: "r"(dst), "l"(__cvta_generic_to_global(src)) : "memory");
}
__device__ __forceinline__ void ldsm_x4(uint32_t* r, uint32_t a) {
    asm volatile("ldmatrix.sync.aligned.m8n8.x4.shared.b16 {%0,%1,%2,%3}, [%4];"
                 : "=r"(r[0]), "=r"(r[1]), "=r"(r[2]), "=r"(r[3]) : "r"(a));
}
__device__ __forceinline__ void ldsm_x4t(uint32_t* r, uint32_t a) {
    asm volatile("ldmatrix.sync.aligned.m8n8.x4.trans.shared.b16 {%0,%1,%2,%3}, [%4];"
                 : "=r"(r[0]), "=r"(r[1]), "=r"(r[2]), "=r"(r[3]) : "r"(a));
}
__device__ __forceinline__ void mma_bf16(float* c, const uint32_t* a, const uint32_t* b) {
    asm volatile(
        "mma.sync.aligned.m16n8k16.row.col.f32.bf16.bf16.f32 "
        "{%0,%1,%2,%3}, {%4,%5,%6,%7}, {%8,%9}, {%0,%1,%2,%3};"
        : "+f"(c[0]), "+f"(c[1]), "+f"(c[2]), "+f"(c[3])
        : "r"(a[0]), "r"(a[1]), "r"(a[2]), "r"(a[3]), "r"(b[0]), "r"(b[1]));
}
__device__ __forceinline__ void split_bf16(float v, __nv_bfloat16& hi, __nv_bfloat16& lo) {
    hi = __float2bfloat16(v);
    lo = __float2bfloat16(v - __bfloat162float(hi));
}

// ============== transpose + split: W[k][n] fp32 -> Whi/Wlo [n][k] bf16 ==============
__global__ __launch_bounds__(256)
void transpose_convert_kernel(const float* __restrict__ W, __nv_bfloat16* __restrict__ Whi,
                              __nv_bfloat16* __restrict__ Wlo, int K, int N)
{
    __shared__ float t[32][33];
    const int k0 = blockIdx.y * 32, n0 = blockIdx.x * 32;
    const int tx = threadIdx.x & 31, ty = threadIdx.x >> 5;   // 32 x 8
#pragma unroll
    for (int j = 0; j < 32; j += 8)
        t[ty + j][tx] = W[(size_t)(k0 + ty + j) * N + n0 + tx];
    __syncthreads();
#pragma unroll
    for (int j = 0; j < 32; j += 8) {
        float v = t[tx][ty + j];
        __nv_bfloat16 hi, lo; split_bf16(v, hi, lo);
        size_t o = (size_t)(n0 + ty + j) * K + k0 + tx;
        Whi[o] = hi; Wlo[o] = lo;
    }
}

// ============== elementwise split: in fp32 -> hi/lo bf16 planes ==============
__global__ __launch_bounds__(256)
void convert_kernel(const float* __restrict__ in, __nv_bfloat16* __restrict__ hi,
                    __nv_bfloat16* __restrict__ lo)
{
    size_t i = ((size_t)blockIdx.x * 256 + threadIdx.x) * 4;
    float4 v = *(const float4*)(in + i);
    __nv_bfloat162 h2a, h2b, l2a, l2b;
    split_bf16(v.x, h2a.x, l2a.x); split_bf16(v.y, h2a.y, l2a.y);
    split_bf16(v.z, h2b.x, l2b.x); split_bf16(v.w, h2b.y, l2b.y);
    *(__nv_bfloat162*)(hi + i)     = h2a;
    *(__nv_bfloat162*)(hi + i + 2) = h2b;
    *(__nv_bfloat162*)(lo + i)     = l2a;
    *(__nv_bfloat162*)(lo + i + 2) = l2b;
}

// ====================== HMMA bf16-split GEMM (512 threads, 16 warps) ======================
// CTA 128x128, warp grid 4x4 (32x32 warp tiles), K-chunk 32, 3-stage cp.async pipeline.
#define ROWB     80
#define PLANE_SZ 10240
#define STAGE_SZ 40960
#define NSTAGE   3
#define MG_SMEM  (NSTAGE * STAGE_SZ)

__device__ __forceinline__ void mg_load_stage(
    uint32_t sb, int stage, const __nv_bfloat16* Ah, const __nv_bfloat16* Al,
    const __nv_bfloat16* Bh, const __nv_bfloat16* Bl, int K, int k0, int tid)
{
    const uint32_t base = sb + stage * STAGE_SZ;
    const int row = tid >> 2;                 // 0..127
    const int g = tid & 3;                    // 0..3
#pragma unroll
    for (int plane = 0; plane < 4; plane++) {
        const __nv_bfloat16* src =
            (plane == 0 ? Ah : plane == 1 ? Al : plane == 2 ? Bh : Bl)
            + (size_t)row * K + k0 + g * 8;
        cp_async16(base + plane * PLANE_SZ + row * ROWB + g * 16, src);
    }
}

__global__ __launch_bounds__(512)
void mma_gemm(const __nv_bfloat16* __restrict__ Ahi, const __nv_bfloat16* __restrict__ Alo,
              const __nv_bfloat16* __restrict__ Bhi, const __nv_bfloat16* __restrict__ Blo,
              const float* __restrict__ bias, const float* __restrict__ resid,
              float* __restrict__ C, __nv_bfloat16* __restrict__ Ohi,
              __nv_bfloat16* __restrict__ Olo, int M, int N, int K, int relu)
{
    extern __shared__ char smem[];
    const uint32_t sb = smem_u32(smem);
    const int tid = threadIdx.x;
    const int wid = tid >> 5, lane = tid & 31;
    const int wm = (wid & 3) * 32;            // warp row offset
    const int wn = (wid >> 2) * 32;           // warp col offset
    const int m0 = blockIdx.y * 128, n0 = blockIdx.x * 128;

    const __nv_bfloat16* Ah = Ahi + (size_t)m0 * K;
    const __nv_bfloat16* Al = Alo + (size_t)m0 * K;
    const __nv_bfloat16* Bh = Bhi + (size_t)n0 * K;
    const __nv_bfloat16* Bl = Blo + (size_t)n0 * K;
    const int NC = K >> 5;

    float acc[2][4][4];
#pragma unroll
    for (int a = 0; a < 2; a++)
#pragma unroll
        for (int b = 0; b < 4; b++)
#pragma unroll
            for (int c = 0; c < 4; c++) acc[a][b][c] = 0.f;

    mg_load_stage(sb, 0, Ah, Al, Bh, Bl, K, 0, tid);  CP_COMMIT();
    mg_load_stage(sb, 1, Ah, Al, Bh, Bl, K, 32, tid); CP_COMMIT();

    const int sub = lane >> 3, brow = lane & 7;

    for (int c = 0; c < NC; c++) {
        if (c + 2 < NC)
            mg_load_stage(sb, (c + 2) % NSTAGE, Ah, Al, Bh, Bl, K, (c + 2) * 32, tid);
        CP_COMMIT();
        CP_WAIT2();
        __syncthreads();

        const uint32_t st = sb + (c % NSTAGE) * STAGE_SZ;
#pragma unroll
        for (int ks = 0; ks < 2; ks++) {
            uint32_t ah[2][4], al[2][4], bh[8], bl[8];
            const uint32_t akoff = ks * 32 + (lane >> 4) * 16;
#pragma unroll
            for (int mi = 0; mi < 2; mi++) {
                uint32_t aaddr = st + (wm + mi * 16 + (lane & 15)) * ROWB + akoff;
                ldsm_x4(ah[mi], aaddr);
                ldsm_x4(al[mi], aaddr + PLANE_SZ);
            }
            const uint32_t bkoff = ks * 32 + (sub & 1) * 16;
#pragma unroll
            for (int nb = 0; nb < 2; nb++) {
                uint32_t baddr = st + 2 * PLANE_SZ
                               + (wn + (nb * 2 + (sub >> 1)) * 8 + brow) * ROWB + bkoff;
                ldsm_x4(&bh[nb * 4], baddr);
                ldsm_x4(&bl[nb * 4], baddr + PLANE_SZ);
            }
#pragma unroll
            for (int mi = 0; mi < 2; mi++)
#pragma unroll
                for (int ni = 0; ni < 4; ni++) {
                    mma_bf16(acc[mi][ni], ah[mi], &bh[ni * 2]);
                    mma_bf16(acc[mi][ni], ah[mi], &bl[ni * 2]);
                    mma_bf16(acc[mi][ni], al[mi], &bh[ni * 2]);
                }
        }
        __syncthreads();
    }

#pragma unroll
    for (int mi = 0; mi < 2; mi++) {
        const int r0 = m0 + wm + mi * 16 + (lane >> 2);
        const int r1 = r0 + 8;
#pragma unroll
        for (int ni = 0; ni < 4; ni++) {
            const int col = n0 + wn + ni * 8 + (lane & 3) * 2;
            float v0 = acc[mi][ni][0], v1 = acc[mi][ni][1];
            float v2 = acc[mi][ni][2], v3 = acc[mi][ni][3];
            if (bias) {
                float b0 = bias[col], b1 = bias[col + 1];
                v0 += b0; v1 += b1; v2 += b0; v3 += b1;
            }
            if (resid) {
                const float* p0 = resid + (size_t)r0 * N + col;
                const float* p1 = resid + (size_t)r1 * N + col;
                v0 += p0[0]; v1 += p0[1]; v2 += p1[0]; v3 += p1[1];
            }
            if (relu) {
                v0 = fmaxf(v0, 0.f); v1 = fmaxf(v1, 0.f);
                v2 = fmaxf(v2, 0.f); v3 = fmaxf(v3, 0.f);
            }
            if (C) {
                *(float2*)(C + (size_t)r0 * N + col) = make_float2(v0, v1);
                *(float2*)(C + (size_t)r1 * N + col) = make_float2(v2, v3);
            }
            if (Ohi) {
                __nv_bfloat162 h0, l0, h1, l1;
                split_bf16(v0, h0.x, l0.x); split_bf16(v1, h0.y, l0.y);
                split_bf16(v2, h1.x, l1.x); split_bf16(v3, h1.y, l1.y);
                *(__nv_bfloat162*)(Ohi + (size_t)r0 * N + col) = h0;
                *(__nv_bfloat162*)(Ohi + (size_t)r1 * N + col) = h1;
                *(__nv_bfloat162*)(Olo + (size_t)r0 * N + col) = l0;
                *(__nv_bfloat162*)(Olo + (size_t)r1 * N + col) = l1;
            }
        }
    }
}

// ====================== fused flash attention (512 threads, split-K) ======================
// One CTA = one (b,h) x 128 query rows. 16 warps: pair (w, w+8) shares rows [16w,16w+16);
// warp w handles keys [0,64), warp w+8 keys [64,128) of each 128-key tile, each with its
// own online softmax; halves merged at the end (exact flash combine).
#define ARB     144                      // smem row bytes (64 bf16 + 16 pad)
#define APLANE  (128 * ARB)              // 18432
#define AT_KV   (2 * APLANE)             // Q hi/lo before this
#define AT_STAGE (4 * APLANE)            // Khi|Klo|Vhi|Vlo
#define AT_SMEM (2 * APLANE + 2 * AT_STAGE)   // 184320

__device__ __forceinline__ void at_load_kv(
    uint32_t base, const __nv_bfloat16* khi, const __nv_bfloat16* klo,
    const __nv_bfloat16* vhi, const __nv_bfloat16* vlo, int tid)
{
#pragma unroll
    for (int j = 0; j < 8; j++) {
        const int plane = j >> 1;              // compile-time: 4 planes x 1024 ops
        int rem = ((j & 1) << 9) + tid;        // 0..1023
        int r = rem >> 3, c = rem & 7;
        const __nv_bfloat16* src =
            (plane == 0 ? khi : plane == 1 ? klo : plane == 2 ? vhi : vlo)
            + (size_t)r * TDM + c * 8;
        cp_async16(base + plane * APLANE + r * ARB + c * 16, src);
    }
}

__global__ __launch_bounds__(512)
void attn_kernel(const __nv_bfloat16* __restrict__ qkvhi,
                 const __nv_bfloat16* __restrict__ qkvlo,
                 __nv_bfloat16* __restrict__ ctxhi,
                 __nv_bfloat16* __restrict__ ctxlo)
{
    extern __shared__ char smem[];
    const uint32_t sb = smem_u32(smem);
    const int tid = threadIdx.x;
    const int wid = tid >> 5, lane = tid & 31;
    const int z = blockIdx.y;                  // b*H + h
    const int b = z >> 4, h = z & 15;
    const int qt0 = blockIdx.x * 128;

    const size_t tok0 = (size_t)b * S;
    const __nv_bfloat16* qh_g = qkvhi + (tok0 + qt0) * TDM + h * 192;
    const __nv_bfloat16* ql_g = qkvlo + (tok0 + qt0) * TDM + h * 192;

    // ---- load Q tile (hi/lo) ----
#pragma unroll
    for (int j = 0; j < 4; j++) {
        const int plane = j >> 1;
        int rem = ((j & 1) << 9) + tid;
        int r = rem >> 3, c = rem & 7;
        const __nv_bfloat16* src = (plane == 0 ? qh_g : ql_g) + (size_t)r * TDM + c * 8;
        cp_async16(sb + plane * APLANE + r * ARB + c * 16, src);
    }
    CP_COMMIT();   // group: Q
    // ---- prologue KV stages 0,1 ----
    {
        const __nv_bfloat16* kh = qkvhi + tok0 * TDM + h * 192 + 64;
        const __nv_bfloat16* kl = qkvlo + tok0 * TDM + h * 192 + 64;
        const __nv_bfloat16* vh = qkvhi + tok0 * TDM + h * 192 + 128;
        const __nv_bfloat16* vl = qkvlo + tok0 * TDM + h * 192 + 128;
        at_load_kv(sb + AT_KV, kh, kl, vh, vl, tid); CP_COMMIT();
        at_load_kv(sb + AT_KV + AT_STAGE, kh + 128 * TDM, kl + 128 * TDM,
                   vh + 128 * TDM, vl + 128 * TDM, tid); CP_COMMIT();
    }

    float oacc[8][4];
#pragma unroll
    for (int i = 0; i < 8; i++)
#pragma unroll
        for (int j = 0; j < 4; j++) oacc[i][j] = 0.f;
    float m0 = -1e30f, m1 = -1e30f, l0 = 0.f, l1 = 0.f;

    const int sub = lane >> 3, brow = lane & 7;
    const int qrow = (wid & 7) * 16 + (lane & 15);
    const int khalf = (wid >> 3) * 64;         // 0 or 64: this warp's key half

    for (int it = 0; it < 16; it++) {
        CP_WAIT1();
        __syncthreads();
        const uint32_t sK = sb + AT_KV + (it & 1) * AT_STAGE;
        const uint32_t sV = sK + 2 * APLANE;

        // ---- S = Q @ K^T over this warp's 64 keys (3-pass hi/lo) ----
        float sacc[8][4];
#pragma unroll
        for (int i = 0; i < 8; i++)
#pragma unroll
            for (int j = 0; j < 4; j++) sacc[i][j] = 0.f;

#pragma unroll
        for (int kg = 0; kg < 4; kg++) {
            uint32_t qh[4], ql[4];
            uint32_t aaddr = sb + qrow * ARB + kg * 32 + (lane >> 4) * 16;
            ldsm_x4(qh, aaddr);
            ldsm_x4(ql, aaddr + APLANE);
#pragma unroll
            for (int ntp = 0; ntp < 4; ntp++) {
                uint32_t kh[4], kl[4];
                uint32_t baddr = sK + (khalf + ntp * 16 + (sub >> 1) * 8 + brow) * ARB
                               + kg * 32 + (sub & 1) * 16;
                ldsm_x4(kh, baddr);
                ldsm_x4(kl, baddr + APLANE);
                mma_bf16(sacc[2 * ntp],     qh, &kh[0]);
                mma_bf16(sacc[2 * ntp],     qh, &kl[0]);
                mma_bf16(sacc[2 * ntp],     ql, &kh[0]);
                mma_bf16(sacc[2 * ntp + 1], qh, &kh[2]);
                mma_bf16(sacc[2 * ntp + 1], qh, &kl[2]);
                mma_bf16(sacc[2 * ntp + 1], ql, &kh[2]);
            }
        }

        // ---- online softmax over this warp's key half ----
        float t0 = -1e30f, t1 = -1e30f;
#pragma unroll
        for (int nt = 0; nt < 8; nt++) {
            t0 = fmaxf(t0, fmaxf(sacc[nt][0], sacc[nt][1]));
            t1 = fmaxf(t1, fmaxf(sacc[nt][2], sacc[nt][3]));
        }
        t0 *= 0.125f; t1 *= 0.125f;
#pragma unroll
        for (int d = 1; d < 4; d <<= 1) {
            t0 = fmaxf(t0, __shfl_xor_sync(0xffffffffu, t0, d));
            t1 = fmaxf(t1, __shfl_xor_sync(0xffffffffu, t1, d));
        }
        float mn0 = fmaxf(m0, t0), mn1 = fmaxf(m1, t1);
        float al0 = __expf(m0 - mn0), al1 = __expf(m1 - mn1);
        m0 = mn0; m1 = mn1;
#pragma unroll
        for (int vt = 0; vt < 8; vt++) {
            oacc[vt][0] *= al0; oacc[vt][1] *= al0;
            oacc[vt][2] *= al1; oacc[vt][3] *= al1;
        }
        l0 *= al0; l1 *= al1;

        // ---- P = exp(S/8 - m), pack bf16 hi/lo fragments ----
        uint32_t phA[8], phB[8], plA[8], plB[8];
        float rs0 = 0.f, rs1 = 0.f;
#pragma unroll
        for (int nt = 0; nt < 8; nt++) {
            float p0 = __expf(fmaf(sacc[nt][0], 0.125f, -mn0));
            float p1 = __expf(fmaf(sacc[nt][1], 0.125f, -mn0));
            float p2 = __expf(fmaf(sacc[nt][2], 0.125f, -mn1));
            float p3 = __expf(fmaf(sacc[nt][3], 0.125f, -mn1));
            rs0 += p0 + p1; rs1 += p2 + p3;
            __nv_bfloat162 hA = __floats2bfloat162_rn(p0, p1);
            __nv_bfloat162 hB = __floats2bfloat162_rn(p2, p3);
            __nv_bfloat162 lA = __floats2bfloat162_rn(p0 - __bfloat162float(hA.x),
                                                      p1 - __bfloat162float(hA.y));
            __nv_bfloat162 lB = __floats2bfloat162_rn(p2 - __bfloat162float(hB.x),
                                                      p3 - __bfloat162float(hB.y));
            phA[nt] = *(uint32_t*)&hA; phB[nt] = *(uint32_t*)&hB;
            plA[nt] = *(uint32_t*)&lA; plB[nt] = *(uint32_t*)&lB;
        }
#pragma unroll
        for (int d = 1; d < 4; d <<= 1) {
            rs0 += __shfl_xor_sync(0xffffffffu, rs0, d);
            rs1 += __shfl_xor_sync(0xffffffffu, rs1, d);
        }
        l0 += rs0; l1 += rs1;

        // ---- O += P @ V over this warp's key half (3-pass hi/lo) ----
#pragma unroll
        for (int kt = 0; kt < 4; kt++) {
            uint32_t pah[4] = {phA[2 * kt], phB[2 * kt], phA[2 * kt + 1], phB[2 * kt + 1]};
            uint32_t pal[4] = {plA[2 * kt], plB[2 * kt], plA[2 * kt + 1], plB[2 * kt + 1]};
#pragma unroll
            for (int vtp = 0; vtp < 4; vtp++) {
                uint32_t vh[4], vl[4];
                uint32_t vaddr = sV + (khalf + kt * 16 + ((lane >> 3) & 1) * 8 + (lane & 7)) * ARB
                               + (vtp * 16 + (lane >> 4) * 8) * 2;
                ldsm_x4t(vh, vaddr);
                ldsm_x4t(vl, vaddr + APLANE);
                mma_bf16(oacc[2 * vtp],     pah, &vh[0]);
                mma_bf16(oacc[2 * vtp],     pah, &vl[0]);
                mma_bf16(oacc[2 * vtp],     pal, &vh[0]);
                mma_bf16(oacc[2 * vtp + 1], pah, &vh[2]);
                mma_bf16(oacc[2 * vtp + 1], pah, &vl[2]);
                mma_bf16(oacc[2 * vtp + 1], pal, &vh[2]);
            }
        }

        __syncthreads();       // done reading this stage
        if (it + 2 < 16) {
            const size_t off = tok0 * TDM + (size_t)(it + 2) * 128 * TDM + h * 192;
            at_load_kv(sb + AT_KV + (it & 1) * AT_STAGE,
                       qkvhi + off + 64, qkvlo + off + 64,
                       qkvhi + off + 128, qkvlo + off + 128, tid);
        }
        CP_COMMIT();
    }

    // ---- merge key-halves: upper warps publish (O, m, l); lower warps combine ----
    __syncthreads();           // all KV reads done; reuse Q area (36 KB) for exchange
    const int r = lane >> 2;
    if (wid >= 8) {
        char* base = smem + (wid - 8) * 4224;
#pragma unroll
        for (int vt = 0; vt < 8; vt++) {
            int coff = vt * 8 + (lane & 3) * 2;
            *(float2*)(base + (r * 64 + coff) * 4)       = make_float2(oacc[vt][0], oacc[vt][1]);
            *(float2*)(base + ((r + 8) * 64 + coff) * 4) = make_float2(oacc[vt][2], oacc[vt][3]);
        }
        if ((lane & 3) == 0) {
            *(float2*)(base + 4096 + r * 8)       = make_float2(m0, l0);
            *(float2*)(base + 4096 + (r + 8) * 8) = make_float2(m1, l1);
        }
    }
    __syncthreads();
    if (wid < 8) {
        char* base = smem + wid * 4224;
        float2 ml0 = *(float2*)(base + 4096 + r * 8);
        float2 ml1 = *(float2*)(base + 4096 + (r + 8) * 8);
        float M0 = fmaxf(m0, ml0.x), M1 = fmaxf(m1, ml1.x);
        float ca0 = __expf(m0 - M0), cb0 = __expf(ml0.x - M0);
        float ca1 = __expf(m1 - M1), cb1 = __expf(ml1.x - M1);
        float inva = 1.f / (l0 * ca0 + ml0.y * cb0);
        float invb = 1.f / (l1 * ca1 + ml1.y * cb1);

        const size_t row0 = tok0 + qt0 + wid * 16 + r;
        const size_t row1 = row0 + 8;
#pragma unroll
        for (int vt = 0; vt < 8; vt++) {
            int coff = vt * 8 + (lane & 3) * 2;
            float2 ob0 = *(float2*)(base + (r * 64 + coff) * 4);
            float2 ob1 = *(float2*)(base + ((r + 8) * 64 + coff) * 4);
            float v0 = (oacc[vt][0] * ca0 + ob0.x * cb0) * inva;
            float v1 = (oacc[vt][1] * ca0 + ob0.y * cb0) * inva;
            float v2 = (oacc[vt][2] * ca1 + ob1.x * cb1) * invb;
            float v3 = (oacc[vt][3] * ca1 + ob1.y * cb1) * invb;
            int col = h * 64 + coff;
            __nv_bfloat162 h0, l0v, h1, l1v;
            split_bf16(v0, h0.x, l0v.x); split_bf16(v1, h0.y, l0v.y);
            split_bf16(v2, h1.x, l1v.x); split_bf16(v3, h1.y, l1v.y);
            *(__nv_bfloat162*)(ctxhi + row0 * DM + col) = h0;
            *(__nv_bfloat162*)(ctxhi + row1 * DM + col) = h1;
            *(__nv_bfloat162*)(ctxlo + row0 * DM + col) = l0v;
            *(__nv_bfloat162*)(ctxlo + row1 * DM + col) = l1v;
        }
    }
}

// --------------- LayerNorm over rows of 1024 (+ optional bf16 planes) ---------------
__global__ __launch_bounds__(256)
void ln_kernel(const float* __restrict__ x, const float* __restrict__ gamma,
               const float* __restrict__ beta, float* __restrict__ out,
               __nv_bfloat16* __restrict__ ohi, __nv_bfloat16* __restrict__ olo)
{
    __shared__ float r1[256];
    __shared__ float r2[256];
    const size_t row = blockIdx.x;
    const float* p = x + row * DM;
    const int tid = threadIdx.x;

    float4 v = *(const float4*)(p + tid * 4);
    float s  = v.x + v.y + v.z + v.w;
    float s2 = v.x * v.x + v.y * v.y + v.z * v.z + v.w * v.w;
    r1[tid] = s; r2[tid] = s2; __syncthreads();
    for (int st = 128; st > 0; st >>= 1) {
        if (tid < st) { r1[tid] += r1[tid + st]; r2[tid] += r2[tid + st]; }
        __syncthreads();
    }
    float mean = r1[0] * (1.f / DM);
    float var  = r2[0] * (1.f / DM) - mean * mean;
    float inv  = rsqrtf(var + EPS);

    float4 g = *(const float4*)(gamma + tid * 4);
    float4 b = *(const float4*)(beta + tid * 4);
    float4 o;
    o.x = (v.x - mean) * inv * g.x + b.x;
    o.y = (v.y - mean) * inv * g.y + b.y;
    o.z = (v.z - mean) * inv * g.z + b.z;
    o.w = (v.w - mean) * inv * g.w + b.w;
    *(float4*)(out + row * DM + tid * 4) = o;

    if (ohi) {
        __nv_bfloat162 h0, l0, h1, l1;
        split_bf16(o.x, h0.x, l0.x); split_bf16(o.y, h0.y, l0.y);
        split_bf16(o.z, h1.x, l1.x); split_bf16(o.w, h1.y, l1.y);
        size_t q = row * DM + tid * 4;
        *(__nv_bfloat162*)(ohi + q)     = h0;
        *(__nv_bfloat162*)(ohi + q + 2) = h1;
        *(__nv_bfloat162*)(olo + q)     = l0;
        *(__nv_bfloat162*)(olo + q + 2) = l1;
    }
}

// ---------------------------------- launch ----------------------------------
extern "C" void kernel_launch(void* const* d_in, const int* in_sizes, int n_in,
                              void* d_out, int out_size)
{
    const float* x      = (const float*)d_in[0];
    const float* W_qkv  = (const float*)d_in[1];
    const float* b_qkv  = (const float*)d_in[2];
    const float* W_o    = (const float*)d_in[3];
    const float* b_o    = (const float*)d_in[4];
    const float* gamma1 = (const float*)d_in[5];
    const float* beta1  = (const float*)d_in[6];
    const float* W1     = (const float*)d_in[7];
    const float* b1     = (const float*)d_in[8];
    const float* W2     = (const float*)d_in[9];
    const float* b2     = (const float*)d_in[10];
    const float* gamma2 = (const float*)d_in[11];
    const float* beta2  = (const float*)d_in[12];
    float* out = (float*)d_out;

    float *tmp, *hbuf;
    __nv_bfloat16 *wbf, *xbf, *qkvbf, *ctxbf, *hbf, *ffnbf;
    cudaGetSymbolAddress((void**)&tmp,    g_tmp);
    cudaGetSymbolAddress((void**)&hbuf,   g_h);
    cudaGetSymbolAddress((void**)&wbf,    g_wbf);
    cudaGetSymbolAddress((void**)&xbf,    g_xbf);
    cudaGetSymbolAddress((void**)&qkvbf,  g_qkvbf);
    cudaGetSymbolAddress((void**)&ctxbf,  g_ctxbf);
    cudaGetSymbolAddress((void**)&hbf,    g_hbf);
    cudaGetSymbolAddress((void**)&ffnbf,  g_ffnbf);

    cudaFuncSetAttribute(mma_gemm, cudaFuncAttributeMaxDynamicSharedMemorySize, MG_SMEM);
    cudaFuncSetAttribute(attn_kernel, cudaFuncAttributeMaxDynamicSharedMemorySize, AT_SMEM);

    const size_t QPL = (size_t)TOK * TDM;   // qkv plane elements
    const size_t DPL = (size_t)TOK * DM;
    const size_t FPL = (size_t)TOK * FFN;

    // 0) weight transpose+split and x split
    transpose_convert_kernel<<<dim3(TDM / 32, DM / 32), 256>>>(W_qkv, wbf + WQKV_HI, wbf + WQKV_LO, DM, TDM);
    transpose_convert_kernel<<<dim3(DM / 32, DM / 32), 256>>>(W_o, wbf + WO_HI, wbf + WO_LO, DM, DM);
    transpose_convert_kernel<<<dim3(FFN / 32, DM / 32), 256>>>(W1, wbf + W1_HI, wbf + W1_LO, DM, FFN);
    transpose_convert_kernel<<<dim3(DM / 32, FFN / 32), 256>>>(W2, wbf + W2_HI, wbf + W2_LO, FFN, DM);
    convert_kernel<<<(TOK * DM) / 1024, 256>>>(x, xbf, xbf + DPL);

    // 1) qkv = x @ W_qkv + b_qkv -> bf16 hi/lo planes
    mma_gemm<<<dim3(TDM / 128, TOK / 128), 512, MG_SMEM>>>(
        xbf, xbf + DPL, wbf + WQKV_HI, wbf + WQKV_LO,
        b_qkv, nullptr, nullptr, qkvbf, qkvbf + QPL, TOK, TDM, DM, 0);

    // 2) fused flash attention -> ctx bf16 hi/lo planes
    attn_kernel<<<dim3(S / 128, BATCH * H), 512, AT_SMEM>>>(
        qkvbf, qkvbf + QPL, ctxbf, ctxbf + DPL);

    // 3) tmp = ctx @ W_o + b_o + x
    mma_gemm<<<dim3(DM / 128, TOK / 128), 512, MG_SMEM>>>(
        ctxbf, ctxbf + DPL, wbf + WO_HI, wbf + WO_LO,
        b_o, x, tmp, nullptr, nullptr, TOK, DM, DM, 0);

    // 4) h = LN1(tmp) + planes
    ln_kernel<<<TOK, 256>>>(tmp, gamma1, beta1, hbuf, hbf, hbf + DPL);

    // 5) ffn = relu(h @ W1 + b1) -> planes only
    mma_gemm<<<dim3(FFN / 128, TOK / 128), 512, MG_SMEM>>>(
        hbf, hbf + DPL, wbf + W1_HI, wbf + W1_LO,
        b1, nullptr, nullptr, ffnbf, ffnbf + FPL, TOK, FFN, DM, 1);

    // 6) tmp = ffn @ W2 + b2 + h
    mma_gemm<<<dim3(DM / 128, TOK / 128), 512, MG_SMEM>>>(
        ffnbf, ffnbf + FPL, wbf + W2_HI, wbf + W2_LO,
        b2, hbuf, tmp, nullptr, nullptr, TOK, DM, FFN, 0);

    // 7) out = LN2(tmp)
    ln_kernel<<<TOK, 256>>>(tmp, gamma2, beta2, out, nullptr, nullptr);
}